// round 14
// baseline (speedup 1.0000x reference)
#include <cuda_runtime.h>
#include <cuda_bf16.h>
#include <math.h>

#define B_ 8
#define C_ 64
#define H_ 128
#define W_ 128
#define HS 256
#define WS 256

__device__ __forceinline__ unsigned long long pack2(float lo, float hi)
{
    unsigned long long r;
    asm("mov.b64 %0, {%1, %2};" : "=l"(r) : "f"(lo), "f"(hi));
    return r;
}
__device__ __forceinline__ float2 unpack2(unsigned long long v)
{
    float lo, hi;
    asm("mov.b64 {%0, %1}, %2;" : "=f"(lo), "=f"(hi) : "l"(v));
    return make_float2(lo, hi);
}
#define FMA2(acc, ww, tt) \
    asm("fma.rn.f32x2 %0, %1, %2, %0;" : "+l"(acc) : "l"(ww), "l"(tt))

__device__ __forceinline__ float4 ldg4_or_zero(const float* p, bool pred)
{
    if (pred) return *(const float4*)p;
    return make_float4(0.f, 0.f, 0.f, 0.f);
}

// per-channel compute+store (R8 inner body, factored)
__device__ __forceinline__ void carafe_body(
    float4 q0, float4 q1, float4 q2,
    const unsigned long long (&wp)[4][9],
    bool z0, bool z31, float* ob)
{
    const unsigned msk = 0xffffffffu;
    float lf0 = __shfl_up_sync(msk, q0.w, 1);
    float lf1 = __shfl_up_sync(msk, q1.w, 1);
    float lf2 = __shfl_up_sync(msk, q2.w, 1);
    float rt0 = __shfl_down_sync(msk, q0.x, 1);
    float rt1 = __shfl_down_sync(msk, q1.x, 1);
    float rt2 = __shfl_down_sync(msk, q2.x, 1);
    if (z0)  { lf0 = 0.f; lf1 = 0.f; lf2 = 0.f; }
    if (z31) { rt0 = 0.f; rt1 = 0.f; rt2 = 0.f; }

    unsigned long long acc00 = 0ull, acc01 = 0ull, acc10 = 0ull, acc11 = 0ull;
    // row 0
    {
        unsigned long long t0 = pack2(lf0, q0.x), t1 = pack2(q0.x, q0.y);
        unsigned long long t2 = pack2(q0.y, q0.z), t3 = pack2(q0.z, q0.w);
        unsigned long long t4 = pack2(q0.w, rt0);
        FMA2(acc00, wp[0][0], t0); FMA2(acc01, wp[1][0], t0);
        FMA2(acc00, wp[0][1], t1); FMA2(acc01, wp[1][1], t1);
        FMA2(acc00, wp[0][2], t2); FMA2(acc01, wp[1][2], t2);
        FMA2(acc10, wp[2][0], t2); FMA2(acc11, wp[3][0], t2);
        FMA2(acc10, wp[2][1], t3); FMA2(acc11, wp[3][1], t3);
        FMA2(acc10, wp[2][2], t4); FMA2(acc11, wp[3][2], t4);
    }
    // row 1
    {
        unsigned long long t0 = pack2(lf1, q1.x), t1 = pack2(q1.x, q1.y);
        unsigned long long t2 = pack2(q1.y, q1.z), t3 = pack2(q1.z, q1.w);
        unsigned long long t4 = pack2(q1.w, rt1);
        FMA2(acc00, wp[0][3], t0); FMA2(acc01, wp[1][3], t0);
        FMA2(acc00, wp[0][4], t1); FMA2(acc01, wp[1][4], t1);
        FMA2(acc00, wp[0][5], t2); FMA2(acc01, wp[1][5], t2);
        FMA2(acc10, wp[2][3], t2); FMA2(acc11, wp[3][3], t2);
        FMA2(acc10, wp[2][4], t3); FMA2(acc11, wp[3][4], t3);
        FMA2(acc10, wp[2][5], t4); FMA2(acc11, wp[3][5], t4);
    }
    // row 2
    {
        unsigned long long t0 = pack2(lf2, q2.x), t1 = pack2(q2.x, q2.y);
        unsigned long long t2 = pack2(q2.y, q2.z), t3 = pack2(q2.z, q2.w);
        unsigned long long t4 = pack2(q2.w, rt2);
        FMA2(acc00, wp[0][6], t0); FMA2(acc01, wp[1][6], t0);
        FMA2(acc00, wp[0][7], t1); FMA2(acc01, wp[1][7], t1);
        FMA2(acc00, wp[0][8], t2); FMA2(acc01, wp[1][8], t2);
        FMA2(acc10, wp[2][6], t2); FMA2(acc11, wp[3][6], t2);
        FMA2(acc10, wp[2][7], t3); FMA2(acc11, wp[3][7], t3);
        FMA2(acc10, wp[2][8], t4); FMA2(acc11, wp[3][8], t4);
    }

    float2 a00 = unpack2(acc00), a01 = unpack2(acc01);
    float2 a10 = unpack2(acc10), a11 = unpack2(acc11);
    __stcs((float4*)ob,       make_float4(a00.x, a01.x, a00.y, a01.y));
    __stcs((float4*)(ob + 4), make_float4(a10.x, a11.x, a10.y, a11.y));
}

// ---------------------------------------------------------------------------
// Fused mean -> weights -> CARAFE. R8 structure; 3 CTAs/SM (no spills) and
// 2-channel batched loads (MLP 6) in the channel loop.
// Block = 128 thr = 4 warps = 2 low-res rows x 2 hi-res sub-rows.
// ---------------------------------------------------------------------------
__global__ void __launch_bounds__(128, 3) carafe_full_kernel(
    const float* __restrict__ x,
    const float* __restrict__ w_off,
    const float* __restrict__ b_off,
    float* __restrict__ out)
{
    __shared__ float sm[4][132];
    __shared__ float sc0[2][2][9];
    __shared__ float sc1[2][2][9];
    __shared__ float sbias[2];

    if (threadIdx.x < 4) {
        int ir = threadIdx.x >> 1, j = threadIdx.x & 1;
        float a0[9], a1[9];
#pragma unroll
        for (int k = 0; k < 9; k++) { a0[k] = 0.f; a1[k] = 0.f; }
#pragma unroll
        for (int pp = 0; pp < 5; pp++)
#pragma unroll
            for (int qq = 0; qq < 5; qq++) {
                int k = (((ir + pp - 2) >> 1) + 1) * 3 + (((j + qq - 2) >> 1) + 1);
                a0[k] += w_off[pp * 5 + qq];
                a1[k] += w_off[25 + pp * 5 + qq];
            }
#pragma unroll
        for (int k = 0; k < 9; k++) { sc0[ir][j][k] = a0[k]; sc1[ir][j][k] = a1[k]; }
    }
    if (threadIdx.x < 2) sbias[threadIdx.x] = b_off[threadIdx.x];

    int b  = blockIdx.x >> 6;
    int y0 = (blockIdx.x & 63) * 2;
    int warp = threadIdx.x >> 5;
    int lane = threadIdx.x & 31;

    // ---- Phase 1: mean of rows y0-1..y0+2, one row per warp, ILP-4 ----
    {
        int yy = y0 - 1 + warp;
        float4 a[4];
#pragma unroll
        for (int i = 0; i < 4; i++) a[i] = make_float4(0.f, 0.f, 0.f, 0.f);
        if (yy >= 0 && yy < H_) {
            const float4* px = (const float4*)(x + ((size_t)b << 20) + yy * W_) + lane;
#pragma unroll
            for (int c = 0; c < C_; c += 4) {
#pragma unroll
                for (int i = 0; i < 4; i++) {
                    float4 v = px[(size_t)(c + i) << 12];
                    a[i].x += v.x; a[i].y += v.y; a[i].z += v.z; a[i].w += v.w;
                }
            }
        }
        const float inv = 1.0f / 64.0f;
        sm[warp][1 + 4 * lane + 0] = (a[0].x + a[1].x + a[2].x + a[3].x) * inv;
        sm[warp][1 + 4 * lane + 1] = (a[0].y + a[1].y + a[2].y + a[3].y) * inv;
        sm[warp][1 + 4 * lane + 2] = (a[0].z + a[1].z + a[2].z + a[3].z) * inv;
        sm[warp][1 + 4 * lane + 3] = (a[0].w + a[1].w + a[2].w + a[3].w) * inv;
        if (lane == 0)  sm[warp][0]   = 0.f;
        if (lane == 31) sm[warp][129] = 0.f;
    }
    __syncthreads();

    int dy = warp & 1;
    int ir = warp >> 1;
    int y = y0 + dy;
    bool hasN = (y > 0), hasS = (y < H_ - 1);

    // ---- Phase 2: weights (identical to R8) ----
    unsigned long long wp[4][9];   // [pp*2+j][k] = {w_pix2pp, w_pix2pp+1}
    {
        float lo[18];
#pragma unroll
        for (int p = 0; p < 4; p++) {
            float m0[9];
#pragma unroll
            for (int r = 0; r < 3; r++)
#pragma unroll
                for (int cc = 0; cc < 3; cc++)
                    m0[r * 3 + cc] = sm[dy + r][4 * lane + p + cc];
            float g9[9];
            float mc = m0[4];
#pragma unroll
            for (int k = 0; k < 9; k++) {
                float d = m0[k] - mc;
                g9[k] = __fdividef(1.0f, d * d + 1.0f);
            }
            float cur[18];
#pragma unroll
            for (int j = 0; j < 2; j++) {
                float o0 = 0.f, o1 = 0.f;
#pragma unroll
                for (int k = 0; k < 9; k++) {
                    o0 = fmaf(m0[k], sc0[ir][j][k], o0);
                    o1 = fmaf(m0[k], sc1[ir][j][k], o1);
                }
                float s0 = (ir ? 0.25f : -0.25f) + 0.25f * tanhf(o0 + sbias[0]);
                float s1 = (j  ? 0.25f : -0.25f) + 0.25f * tanhf(o1 + sbias[1]);
                float lv[9];
                float sum = 0.f;
#pragma unroll
                for (int k = 0; k < 9; k++) {
                    float d0 = s0 - (float)(k / 3 - 1);
                    float d1 = s1 - (float)(k % 3 - 1);
                    float ker = __fdividef(1.0f, d0 * d0 + d1 * d1 + 0.5f);
                    lv[k] = __expf(g9[k] * ker);   // arg in (0,2]: no max-sub
                    sum += lv[k];
                }
                float sinv = __fdividef(1.0f, sum);
#pragma unroll
                for (int k = 0; k < 9; k++) cur[j * 9 + k] = lv[k] * sinv;
            }
            if ((p & 1) == 0) {
#pragma unroll
                for (int t = 0; t < 18; t++) lo[t] = cur[t];
            } else {
#pragma unroll
                for (int j = 0; j < 2; j++)
#pragma unroll
                    for (int k = 0; k < 9; k++)
                        wp[(p >> 1) * 2 + j][k] = pack2(lo[j * 9 + k], cur[j * 9 + k]);
            }
        }
    }

    // ---- Phase 3: channel loop, 2 channels per iteration (MLP 6) ----
    const float* px = x + ((size_t)b << 20) + y * W_ + 4 * lane;
    float* ob = out + (size_t)(b * C_) * (HS * WS)
                    + (size_t)(2 * y + ir) * WS + 8 * lane;
    bool z0 = (lane == 0), z31 = (lane == 31);

#pragma unroll 1
    for (int c = 0; c < C_; c += 2) {
        // batch both channels' loads first
        float4 qa0 = ldg4_or_zero(px - W_, hasN);
        float4 qa1 = *(const float4*)px;
        float4 qa2 = ldg4_or_zero(px + W_, hasS);
        const float* px2 = px + 16384;
        float4 qb0 = ldg4_or_zero(px2 - W_, hasN);
        float4 qb1 = *(const float4*)px2;
        float4 qb2 = ldg4_or_zero(px2 + W_, hasS);

        carafe_body(qa0, qa1, qa2, wp, z0, z31, ob);
        carafe_body(qb0, qb1, qb2, wp, z0, z31, ob + (size_t)HS * WS);

        px += 2 * 16384;
        ob += 2 * (size_t)HS * WS;
    }
}

extern "C" void kernel_launch(void* const* d_in, const int* in_sizes, int n_in,
                              void* d_out, int out_size)
{
    const float* x     = (const float*)d_in[0];   // [8,64,128,128]
    const float* w_off = (const float*)d_in[1];   // [2,1,5,5]
    const float* b_off = (const float*)d_in[2];   // [2]
    float* out = (float*)d_out;                   // [8,64,256,256]

    carafe_full_kernel<<<B_ * H_ / 2, 128>>>(x, w_off, b_off, out);
}

// round 16
// speedup vs baseline: 1.2609x; 1.2609x over previous
#include <cuda_runtime.h>
#include <cuda_bf16.h>
#include <math.h>

#define B_ 8
#define C_ 64
#define H_ 128
#define W_ 128
#define HS 256
#define WS 256

__device__ __forceinline__ unsigned long long pack2(float lo, float hi)
{
    unsigned long long r;
    asm("mov.b64 %0, {%1, %2};" : "=l"(r) : "f"(lo), "f"(hi));
    return r;
}
__device__ __forceinline__ float2 unpack2(unsigned long long v)
{
    float lo, hi;
    asm("mov.b64 {%0, %1}, %2;" : "=f"(lo), "=f"(hi) : "l"(v));
    return make_float2(lo, hi);
}
#define FMA2(acc, ww, tt) \
    asm("fma.rn.f32x2 %0, %1, %2, %0;" : "+l"(acc) : "l"(ww), "l"(tt))

__device__ __forceinline__ void cp_async16cg(unsigned dst, const float* src)
{
    asm volatile("cp.async.cg.shared.global [%0], [%1], 16;"
                 :: "r"(dst), "l"(src) : "memory");
}
__device__ __forceinline__ void cp_commit()
{
    asm volatile("cp.async.commit_group;" ::: "memory");
}

// ---------------------------------------------------------------------------
// Fused mean -> weights -> CARAFE with block-cooperative cp.async staging.
// Block = 128 thr = 4 warps = 2 low-res rows x 2 hi-res sub-rows.
// Per channel: each thread cp.asyncs ONE 16B chunk (warp w stages row w) into
// a 3-buffer smem tile; depth-2 prefetch; one __syncthreads per channel;
// consume via LDS.128. Weights/FMA2/stores identical to R8.
// ---------------------------------------------------------------------------
__global__ void __launch_bounds__(128, 4) carafe_full_kernel(
    const float* __restrict__ x,
    const float* __restrict__ w_off,
    const float* __restrict__ b_off,
    float* __restrict__ out)
{
    __shared__ float sm[4][132];
    __shared__ float sc0[2][2][9];
    __shared__ float sc1[2][2][9];
    __shared__ float sbias[2];
    __shared__ __align__(16) float stage[3][4][128];   // buf, row, col

    if (threadIdx.x < 4) {
        int ir = threadIdx.x >> 1, j = threadIdx.x & 1;
        float a0[9], a1[9];
#pragma unroll
        for (int k = 0; k < 9; k++) { a0[k] = 0.f; a1[k] = 0.f; }
#pragma unroll
        for (int pp = 0; pp < 5; pp++)
#pragma unroll
            for (int qq = 0; qq < 5; qq++) {
                int k = (((ir + pp - 2) >> 1) + 1) * 3 + (((j + qq - 2) >> 1) + 1);
                a0[k] += w_off[pp * 5 + qq];
                a1[k] += w_off[25 + pp * 5 + qq];
            }
#pragma unroll
        for (int k = 0; k < 9; k++) { sc0[ir][j][k] = a0[k]; sc1[ir][j][k] = a1[k]; }
    }
    if (threadIdx.x < 2) sbias[threadIdx.x] = b_off[threadIdx.x];

    int b  = blockIdx.x >> 6;
    int y0 = (blockIdx.x & 63) * 2;
    int warp = threadIdx.x >> 5;
    int lane = threadIdx.x & 31;

    // ---- Phase 1: mean of rows y0-1..y0+2, one row per warp, ILP-4 ----
    {
        int yy = y0 - 1 + warp;
        float4 a[4];
#pragma unroll
        for (int i = 0; i < 4; i++) a[i] = make_float4(0.f, 0.f, 0.f, 0.f);
        if (yy >= 0 && yy < H_) {
            const float4* px = (const float4*)(x + ((size_t)b << 20) + yy * W_) + lane;
#pragma unroll
            for (int c = 0; c < C_; c += 4) {
#pragma unroll
                for (int i = 0; i < 4; i++) {
                    float4 v = px[(size_t)(c + i) << 12];
                    a[i].x += v.x; a[i].y += v.y; a[i].z += v.z; a[i].w += v.w;
                }
            }
        }
        const float inv = 1.0f / 64.0f;
        sm[warp][1 + 4 * lane + 0] = (a[0].x + a[1].x + a[2].x + a[3].x) * inv;
        sm[warp][1 + 4 * lane + 1] = (a[0].y + a[1].y + a[2].y + a[3].y) * inv;
        sm[warp][1 + 4 * lane + 2] = (a[0].z + a[1].z + a[2].z + a[3].z) * inv;
        sm[warp][1 + 4 * lane + 3] = (a[0].w + a[1].w + a[2].w + a[3].w) * inv;
        if (lane == 0)  sm[warp][0]   = 0.f;
        if (lane == 31) sm[warp][129] = 0.f;
    }
    __syncthreads();

    int dy = warp & 1;
    int ir = warp >> 1;
    int y = y0 + dy;

    // ---- Phase 2: weights (identical to R8) ----
    unsigned long long wp[4][9];   // [pp*2+j][k] = {w_pix2pp, w_pix2pp+1}
    {
        float lo[18];
#pragma unroll
        for (int p = 0; p < 4; p++) {
            float m0[9];
#pragma unroll
            for (int r = 0; r < 3; r++)
#pragma unroll
                for (int cc = 0; cc < 3; cc++)
                    m0[r * 3 + cc] = sm[dy + r][4 * lane + p + cc];
            float g9[9];
            float mc = m0[4];
#pragma unroll
            for (int k = 0; k < 9; k++) {
                float d = m0[k] - mc;
                g9[k] = __fdividef(1.0f, d * d + 1.0f);
            }
            float cur[18];
#pragma unroll
            for (int j = 0; j < 2; j++) {
                float o0 = 0.f, o1 = 0.f;
#pragma unroll
                for (int k = 0; k < 9; k++) {
                    o0 = fmaf(m0[k], sc0[ir][j][k], o0);
                    o1 = fmaf(m0[k], sc1[ir][j][k], o1);
                }
                float s0 = (ir ? 0.25f : -0.25f) + 0.25f * tanhf(o0 + sbias[0]);
                float s1 = (j  ? 0.25f : -0.25f) + 0.25f * tanhf(o1 + sbias[1]);
                float lv[9];
                float sum = 0.f;
#pragma unroll
                for (int k = 0; k < 9; k++) {
                    float d0 = s0 - (float)(k / 3 - 1);
                    float d1 = s1 - (float)(k % 3 - 1);
                    float ker = __fdividef(1.0f, d0 * d0 + d1 * d1 + 0.5f);
                    lv[k] = __expf(g9[k] * ker);   // arg in (0,2]: no max-sub
                    sum += lv[k];
                }
                float sinv = __fdividef(1.0f, sum);
#pragma unroll
                for (int k = 0; k < 9; k++) cur[j * 9 + k] = lv[k] * sinv;
            }
            if ((p & 1) == 0) {
#pragma unroll
                for (int t = 0; t < 18; t++) lo[t] = cur[t];
            } else {
#pragma unroll
                for (int j = 0; j < 2; j++)
#pragma unroll
                    for (int k = 0; k < 9; k++)
                        wp[(p >> 1) * 2 + j][k] = pack2(lo[j * 9 + k], cur[j * 9 + k]);
            }
        }
    }

    // ---- Phase 3: staged channel loop ----
    // This thread stages: row (y0-1+warp), chunk cols 4*lane..4*lane+3.
    int yrow = y0 - 1 + warp;
    bool rowok = (yrow >= 0 && yrow < H_);
    const float* psrc = x + ((size_t)b << 20) + yrow * W_ + 4 * lane;  // ch 0

    // pre-zero this thread's chunk in all 3 buffers if its row is padding
    if (!rowok) {
#pragma unroll
        for (int t = 0; t < 3; t++)
            *(float4*)&stage[t][warp][4 * lane] = make_float4(0.f, 0.f, 0.f, 0.f);
    }

    unsigned sdst0 = (unsigned)__cvta_generic_to_shared(&stage[0][warp][4 * lane]);
    const unsigned BUFB = 4 * 128 * 4;   // bytes per buffer

    // prologue: stage channels 0 (buf0) and 1 (buf1)
    if (rowok) cp_async16cg(sdst0, psrc);
    cp_commit();
    if (rowok) cp_async16cg(sdst0 + BUFB, psrc + 16384);
    cp_commit();

    const float* pfetch = psrc + 2 * 16384;

    const float* srd_base = &stage[0][dy][4 * lane];  // consume base, buf 0
    float* ob = out + (size_t)(b * C_) * (HS * WS)
                    + (size_t)(2 * y + ir) * WS + 8 * lane;
    bool z0 = (lane == 0), z31 = (lane == 31);
    const unsigned msk = 0xffffffffu;

    int bi = 0;     // buffer holding channel c
    int fb = 2;     // buffer to refill with channel c+2

#pragma unroll 1
    for (int c = 0; c < C_; c++) {
        if (c < C_ - 1) asm volatile("cp.async.wait_group 1;" ::: "memory");
        else            asm volatile("cp.async.wait_group 0;" ::: "memory");
        __syncthreads();   // c's buffer visible; all reads of c-1 complete

        // refill buffer fb with channel c+2 (fb == (c-1)%3, safe to overwrite)
        if (c + 2 < C_) {
            if (rowok) cp_async16cg(sdst0 + (unsigned)fb * BUFB, pfetch);
            cp_commit();
            pfetch += 16384;
        }

        const float* srd = srd_base + bi * (4 * 128);
        float4 q0 = *(const float4*)(srd);
        float4 q1 = *(const float4*)(srd + 128);
        float4 q2 = *(const float4*)(srd + 256);

        float lf0 = __shfl_up_sync(msk, q0.w, 1);
        float lf1 = __shfl_up_sync(msk, q1.w, 1);
        float lf2 = __shfl_up_sync(msk, q2.w, 1);
        float rt0 = __shfl_down_sync(msk, q0.x, 1);
        float rt1 = __shfl_down_sync(msk, q1.x, 1);
        float rt2 = __shfl_down_sync(msk, q2.x, 1);
        if (z0)  { lf0 = 0.f; lf1 = 0.f; lf2 = 0.f; }
        if (z31) { rt0 = 0.f; rt1 = 0.f; rt2 = 0.f; }

        unsigned long long acc00 = 0ull, acc01 = 0ull, acc10 = 0ull, acc11 = 0ull;
        // row 0
        {
            unsigned long long t0 = pack2(lf0, q0.x), t1 = pack2(q0.x, q0.y);
            unsigned long long t2 = pack2(q0.y, q0.z), t3 = pack2(q0.z, q0.w);
            unsigned long long t4 = pack2(q0.w, rt0);
            FMA2(acc00, wp[0][0], t0); FMA2(acc01, wp[1][0], t0);
            FMA2(acc00, wp[0][1], t1); FMA2(acc01, wp[1][1], t1);
            FMA2(acc00, wp[0][2], t2); FMA2(acc01, wp[1][2], t2);
            FMA2(acc10, wp[2][0], t2); FMA2(acc11, wp[3][0], t2);
            FMA2(acc10, wp[2][1], t3); FMA2(acc11, wp[3][1], t3);
            FMA2(acc10, wp[2][2], t4); FMA2(acc11, wp[3][2], t4);
        }
        // row 1
        {
            unsigned long long t0 = pack2(lf1, q1.x), t1 = pack2(q1.x, q1.y);
            unsigned long long t2 = pack2(q1.y, q1.z), t3 = pack2(q1.z, q1.w);
            unsigned long long t4 = pack2(q1.w, rt1);
            FMA2(acc00, wp[0][3], t0); FMA2(acc01, wp[1][3], t0);
            FMA2(acc00, wp[0][4], t1); FMA2(acc01, wp[1][4], t1);
            FMA2(acc00, wp[0][5], t2); FMA2(acc01, wp[1][5], t2);
            FMA2(acc10, wp[2][3], t2); FMA2(acc11, wp[3][3], t2);
            FMA2(acc10, wp[2][4], t3); FMA2(acc11, wp[3][4], t3);
            FMA2(acc10, wp[2][5], t4); FMA2(acc11, wp[3][5], t4);
        }
        // row 2
        {
            unsigned long long t0 = pack2(lf2, q2.x), t1 = pack2(q2.x, q2.y);
            unsigned long long t2 = pack2(q2.y, q2.z), t3 = pack2(q2.z, q2.w);
            unsigned long long t4 = pack2(q2.w, rt2);
            FMA2(acc00, wp[0][6], t0); FMA2(acc01, wp[1][6], t0);
            FMA2(acc00, wp[0][7], t1); FMA2(acc01, wp[1][7], t1);
            FMA2(acc00, wp[0][8], t2); FMA2(acc01, wp[1][8], t2);
            FMA2(acc10, wp[2][6], t2); FMA2(acc11, wp[3][6], t2);
            FMA2(acc10, wp[2][7], t3); FMA2(acc11, wp[3][7], t3);
            FMA2(acc10, wp[2][8], t4); FMA2(acc11, wp[3][8], t4);
        }

        float2 a00 = unpack2(acc00), a01 = unpack2(acc01);
        float2 a10 = unpack2(acc10), a11 = unpack2(acc11);

        __stcs((float4*)ob,       make_float4(a00.x, a01.x, a00.y, a01.y));
        __stcs((float4*)(ob + 4), make_float4(a10.x, a11.x, a10.y, a11.y));

        ob += (size_t)HS * WS;
        bi = (bi == 2) ? 0 : bi + 1;
        fb = (fb == 2) ? 0 : fb + 1;
    }
}

extern "C" void kernel_launch(void* const* d_in, const int* in_sizes, int n_in,
                              void* d_out, int out_size)
{
    const float* x     = (const float*)d_in[0];   // [8,64,128,128]
    const float* w_off = (const float*)d_in[1];   // [2,1,5,5]
    const float* b_off = (const float*)d_in[2];   // [2]
    float* out = (float*)d_out;                   // [8,64,256,256]

    carafe_full_kernel<<<B_ * H_ / 2, 128>>>(x, w_off, b_off, out);
}

// round 17
// speedup vs baseline: 1.2617x; 1.0007x over previous
#include <cuda_runtime.h>
#include <cuda_bf16.h>
#include <math.h>

#define B_ 8
#define C_ 64
#define H_ 128
#define W_ 128
#define HS 256
#define WS 256
#define NBUF 6

__device__ __forceinline__ unsigned long long pack2(float lo, float hi)
{
    unsigned long long r;
    asm("mov.b64 %0, {%1, %2};" : "=l"(r) : "f"(lo), "f"(hi));
    return r;
}
__device__ __forceinline__ float2 unpack2(unsigned long long v)
{
    float lo, hi;
    asm("mov.b64 {%0, %1}, %2;" : "=f"(lo), "=f"(hi) : "l"(v));
    return make_float2(lo, hi);
}
#define FMA2(acc, ww, tt) \
    asm("fma.rn.f32x2 %0, %1, %2, %0;" : "+l"(acc) : "l"(ww), "l"(tt))

__device__ __forceinline__ void cp_async16cg(unsigned dst, const float* src)
{
    asm volatile("cp.async.cg.shared.global [%0], [%1], 16;"
                 :: "r"(dst), "l"(src) : "memory");
}
__device__ __forceinline__ void cp_commit()
{
    asm volatile("cp.async.commit_group;" ::: "memory");
}

// ---------------------------------------------------------------------------
// Fused mean -> weights -> CARAFE, block-cooperative cp.async staging with a
// DEEP pipeline: 6 buffers, prefetch distance 5 (covers DRAM latency).
// Block = 128 thr = 4 warps = 2 low-res rows x 2 hi-res sub-rows.
// ---------------------------------------------------------------------------
__global__ void __launch_bounds__(128, 4) carafe_full_kernel(
    const float* __restrict__ x,
    const float* __restrict__ w_off,
    const float* __restrict__ b_off,
    float* __restrict__ out)
{
    __shared__ float sm[4][132];
    __shared__ float sc0[2][2][9];
    __shared__ float sc1[2][2][9];
    __shared__ float sbias[2];
    __shared__ __align__(16) float stage[NBUF][4][128];   // buf, row, col

    if (threadIdx.x < 4) {
        int ir = threadIdx.x >> 1, j = threadIdx.x & 1;
        float a0[9], a1[9];
#pragma unroll
        for (int k = 0; k < 9; k++) { a0[k] = 0.f; a1[k] = 0.f; }
#pragma unroll
        for (int pp = 0; pp < 5; pp++)
#pragma unroll
            for (int qq = 0; qq < 5; qq++) {
                int k = (((ir + pp - 2) >> 1) + 1) * 3 + (((j + qq - 2) >> 1) + 1);
                a0[k] += w_off[pp * 5 + qq];
                a1[k] += w_off[25 + pp * 5 + qq];
            }
#pragma unroll
        for (int k = 0; k < 9; k++) { sc0[ir][j][k] = a0[k]; sc1[ir][j][k] = a1[k]; }
    }
    if (threadIdx.x < 2) sbias[threadIdx.x] = b_off[threadIdx.x];

    int b  = blockIdx.x >> 6;
    int y0 = (blockIdx.x & 63) * 2;
    int warp = threadIdx.x >> 5;
    int lane = threadIdx.x & 31;

    // ---- Phase 1: mean of rows y0-1..y0+2, one row per warp, ILP-4 ----
    {
        int yy = y0 - 1 + warp;
        float4 a[4];
#pragma unroll
        for (int i = 0; i < 4; i++) a[i] = make_float4(0.f, 0.f, 0.f, 0.f);
        if (yy >= 0 && yy < H_) {
            const float4* px = (const float4*)(x + ((size_t)b << 20) + yy * W_) + lane;
#pragma unroll
            for (int c = 0; c < C_; c += 4) {
#pragma unroll
                for (int i = 0; i < 4; i++) {
                    float4 v = px[(size_t)(c + i) << 12];
                    a[i].x += v.x; a[i].y += v.y; a[i].z += v.z; a[i].w += v.w;
                }
            }
        }
        const float inv = 1.0f / 64.0f;
        sm[warp][1 + 4 * lane + 0] = (a[0].x + a[1].x + a[2].x + a[3].x) * inv;
        sm[warp][1 + 4 * lane + 1] = (a[0].y + a[1].y + a[2].y + a[3].y) * inv;
        sm[warp][1 + 4 * lane + 2] = (a[0].z + a[1].z + a[2].z + a[3].z) * inv;
        sm[warp][1 + 4 * lane + 3] = (a[0].w + a[1].w + a[2].w + a[3].w) * inv;
        if (lane == 0)  sm[warp][0]   = 0.f;
        if (lane == 31) sm[warp][129] = 0.f;
    }
    __syncthreads();

    int dy = warp & 1;
    int ir = warp >> 1;
    int y = y0 + dy;

    // ---- Phase 2: weights (identical to R8) ----
    unsigned long long wp[4][9];   // [pp*2+j][k] = {w_pix2pp, w_pix2pp+1}
    {
        float lo[18];
#pragma unroll
        for (int p = 0; p < 4; p++) {
            float m0[9];
#pragma unroll
            for (int r = 0; r < 3; r++)
#pragma unroll
                for (int cc = 0; cc < 3; cc++)
                    m0[r * 3 + cc] = sm[dy + r][4 * lane + p + cc];
            float g9[9];
            float mc = m0[4];
#pragma unroll
            for (int k = 0; k < 9; k++) {
                float d = m0[k] - mc;
                g9[k] = __fdividef(1.0f, d * d + 1.0f);
            }
            float cur[18];
#pragma unroll
            for (int j = 0; j < 2; j++) {
                float o0 = 0.f, o1 = 0.f;
#pragma unroll
                for (int k = 0; k < 9; k++) {
                    o0 = fmaf(m0[k], sc0[ir][j][k], o0);
                    o1 = fmaf(m0[k], sc1[ir][j][k], o1);
                }
                float s0 = (ir ? 0.25f : -0.25f) + 0.25f * tanhf(o0 + sbias[0]);
                float s1 = (j  ? 0.25f : -0.25f) + 0.25f * tanhf(o1 + sbias[1]);
                float lv[9];
                float sum = 0.f;
#pragma unroll
                for (int k = 0; k < 9; k++) {
                    float d0 = s0 - (float)(k / 3 - 1);
                    float d1 = s1 - (float)(k % 3 - 1);
                    float ker = __fdividef(1.0f, d0 * d0 + d1 * d1 + 0.5f);
                    lv[k] = __expf(g9[k] * ker);   // arg in (0,2]: no max-sub
                    sum += lv[k];
                }
                float sinv = __fdividef(1.0f, sum);
#pragma unroll
                for (int k = 0; k < 9; k++) cur[j * 9 + k] = lv[k] * sinv;
            }
            if ((p & 1) == 0) {
#pragma unroll
                for (int t = 0; t < 18; t++) lo[t] = cur[t];
            } else {
#pragma unroll
                for (int j = 0; j < 2; j++)
#pragma unroll
                    for (int k = 0; k < 9; k++)
                        wp[(p >> 1) * 2 + j][k] = pack2(lo[j * 9 + k], cur[j * 9 + k]);
            }
        }
    }

    // ---- Phase 3: deep-pipelined staged channel loop ----
    // This thread stages: row (y0-1+warp), chunk cols 4*lane..4*lane+3.
    int yrow = y0 - 1 + warp;
    bool rowok = (yrow >= 0 && yrow < H_);
    const float* psrc = x + ((size_t)b << 20) + yrow * W_ + 4 * lane;  // ch 0

    // pre-zero this thread's chunk in all buffers if its row is padding
    if (!rowok) {
#pragma unroll
        for (int t = 0; t < NBUF; t++)
            *(float4*)&stage[t][warp][4 * lane] = make_float4(0.f, 0.f, 0.f, 0.f);
    }

    unsigned sdst0 = (unsigned)__cvta_generic_to_shared(&stage[0][warp][4 * lane]);
    const unsigned BUFB = 4 * 128 * 4;   // bytes per buffer

    // prologue: stage channels 0..4 into buffers 0..4 (one group each)
#pragma unroll
    for (int k = 0; k < NBUF - 1; k++) {
        if (rowok) cp_async16cg(sdst0 + (unsigned)k * BUFB, psrc + k * 16384);
        cp_commit();
    }
    const float* pfetch = psrc + (NBUF - 1) * 16384;

    const float* srd_base = &stage[0][dy][4 * lane];  // consume base, buf 0
    float* ob = out + (size_t)(b * C_) * (HS * WS)
                    + (size_t)(2 * y + ir) * WS + 8 * lane;
    bool z0 = (lane == 0), z31 = (lane == 31);
    const unsigned msk = 0xffffffffu;

    int bi = 0;           // buffer holding channel c
    int fb = NBUF - 1;    // buffer to refill with channel c+NBUF-1

#pragma unroll 1
    for (int c = 0; c < C_; c++) {
        // guarantee channel c's group complete:
        if (c < C_ - (NBUF - 1))
            asm volatile("cp.async.wait_group %0;" :: "n"(NBUF - 2) : "memory");
        else
            asm volatile("cp.async.wait_group 0;" ::: "memory");
        __syncthreads();   // c's buffer visible; all reads of c-1 complete

        // refill buffer fb with channel c+5 (fb == (c-1)%NBUF, WAR-safe)
        if (c + NBUF - 1 < C_) {
            if (rowok) cp_async16cg(sdst0 + (unsigned)fb * BUFB, pfetch);
            cp_commit();
            pfetch += 16384;
        }

        const float* srd = srd_base + bi * (4 * 128);
        float4 q0 = *(const float4*)(srd);
        float4 q1 = *(const float4*)(srd + 128);
        float4 q2 = *(const float4*)(srd + 256);

        float lf0 = __shfl_up_sync(msk, q0.w, 1);
        float lf1 = __shfl_up_sync(msk, q1.w, 1);
        float lf2 = __shfl_up_sync(msk, q2.w, 1);
        float rt0 = __shfl_down_sync(msk, q0.x, 1);
        float rt1 = __shfl_down_sync(msk, q1.x, 1);
        float rt2 = __shfl_down_sync(msk, q2.x, 1);
        if (z0)  { lf0 = 0.f; lf1 = 0.f; lf2 = 0.f; }
        if (z31) { rt0 = 0.f; rt1 = 0.f; rt2 = 0.f; }

        unsigned long long acc00 = 0ull, acc01 = 0ull, acc10 = 0ull, acc11 = 0ull;
        // row 0
        {
            unsigned long long t0 = pack2(lf0, q0.x), t1 = pack2(q0.x, q0.y);
            unsigned long long t2 = pack2(q0.y, q0.z), t3 = pack2(q0.z, q0.w);
            unsigned long long t4 = pack2(q0.w, rt0);
            FMA2(acc00, wp[0][0], t0); FMA2(acc01, wp[1][0], t0);
            FMA2(acc00, wp[0][1], t1); FMA2(acc01, wp[1][1], t1);
            FMA2(acc00, wp[0][2], t2); FMA2(acc01, wp[1][2], t2);
            FMA2(acc10, wp[2][0], t2); FMA2(acc11, wp[3][0], t2);
            FMA2(acc10, wp[2][1], t3); FMA2(acc11, wp[3][1], t3);
            FMA2(acc10, wp[2][2], t4); FMA2(acc11, wp[3][2], t4);
        }
        // row 1
        {
            unsigned long long t0 = pack2(lf1, q1.x), t1 = pack2(q1.x, q1.y);
            unsigned long long t2 = pack2(q1.y, q1.z), t3 = pack2(q1.z, q1.w);
            unsigned long long t4 = pack2(q1.w, rt1);
            FMA2(acc00, wp[0][3], t0); FMA2(acc01, wp[1][3], t0);
            FMA2(acc00, wp[0][4], t1); FMA2(acc01, wp[1][4], t1);
            FMA2(acc00, wp[0][5], t2); FMA2(acc01, wp[1][5], t2);
            FMA2(acc10, wp[2][3], t2); FMA2(acc11, wp[3][3], t2);
            FMA2(acc10, wp[2][4], t3); FMA2(acc11, wp[3][4], t3);
            FMA2(acc10, wp[2][5], t4); FMA2(acc11, wp[3][5], t4);
        }
        // row 2
        {
            unsigned long long t0 = pack2(lf2, q2.x), t1 = pack2(q2.x, q2.y);
            unsigned long long t2 = pack2(q2.y, q2.z), t3 = pack2(q2.z, q2.w);
            unsigned long long t4 = pack2(q2.w, rt2);
            FMA2(acc00, wp[0][6], t0); FMA2(acc01, wp[1][6], t0);
            FMA2(acc00, wp[0][7], t1); FMA2(acc01, wp[1][7], t1);
            FMA2(acc00, wp[0][8], t2); FMA2(acc01, wp[1][8], t2);
            FMA2(acc10, wp[2][6], t2); FMA2(acc11, wp[3][6], t2);
            FMA2(acc10, wp[2][7], t3); FMA2(acc11, wp[3][7], t3);
            FMA2(acc10, wp[2][8], t4); FMA2(acc11, wp[3][8], t4);
        }

        float2 a00 = unpack2(acc00), a01 = unpack2(acc01);
        float2 a10 = unpack2(acc10), a11 = unpack2(acc11);

        __stcs((float4*)ob,       make_float4(a00.x, a01.x, a00.y, a01.y));
        __stcs((float4*)(ob + 4), make_float4(a10.x, a11.x, a10.y, a11.y));

        ob += (size_t)HS * WS;
        bi = (bi == NBUF - 1) ? 0 : bi + 1;
        fb = (fb == NBUF - 1) ? 0 : fb + 1;
    }
}

extern "C" void kernel_launch(void* const* d_in, const int* in_sizes, int n_in,
                              void* d_out, int out_size)
{
    const float* x     = (const float*)d_in[0];   // [8,64,128,128]
    const float* w_off = (const float*)d_in[1];   // [2,1,5,5]
    const float* b_off = (const float*)d_in[2];   // [2]
    float* out = (float*)d_out;                   // [8,64,256,256]

    carafe_full_kernel<<<B_ * H_ / 2, 128>>>(x, w_off, b_off, out);
}